// round 15
// baseline (speedup 1.0000x reference)
#include <cuda_runtime.h>
#include <cuda_fp16.h>
#include <math.h>

// ----------------------------------------------------------------------------
// HyperGraphModel on GB300.
//  - 4 big H-GEMMs in fp16 (HMMA m16n8k16, fp32 accum, ldmatrix fragments,
//    3-stage BK=64 cp.async pipeline, ONE barrier per k-tile, 2 CTAs/SM).
//  - Dynamic pow-2 scaling: amax fused into producing epilogues. For split-K
//    outputs (Mm) the epilogue records max|partial|*S — a provable upper
//    bound on the true amax (|sum| <= S*max|partial|); overshoot <=S only
//    costs exponent headroom, not relative precision.
//  - H->fp16 conversion is CHUNKED on a side stream; hgemm layer-1 trans is
//    split into two gated launches so conversion overlaps its execution.
//  - All scratch prep (resets/zeros/weight rounding) rides the side stream.
//  NOTE: tcgen05 unavailable — ptxas here targets sm_103 (no 'a'), verified
//  round 12.
// ----------------------------------------------------------------------------

#define BM 256           // tf32 kernel M tile
#define BK 32            // tf32 kernel k-tile
#define HBM 128          // fp16 kernel M tile (2 CTAs/SM)
#define HBK 64           // fp16 kernel k-tile
#define STAGES 3         // tf32 stages
#define HST 3            // fp16 stages

// fp32 scratch: X0,X1,X2,Yf (4*N*D) + Mm0 (E*D) + Mm1 (E*D) + Wtr + W1r + W2r
__device__ float g_buf[12500000];
// fp16 scratch: Hh (N*E) + Yh (N*D) + Mmh (E*D)
__device__ __align__(256) __half g_hbuf[163600000];
// scale slots: [0]=amaxY0 [1]=amaxY1 [2]=amaxM0 [3]=amaxM1
__device__ unsigned g_sc[8];

// ---------------- common helpers ----------------
__device__ __forceinline__ unsigned f2tf32(unsigned x) {
    unsigned r;
    asm("cvt.rna.tf32.f32 %0, %1;" : "=r"(r) : "r"(x));
    return r;
}
__device__ __forceinline__ float roundtf(float x) {
    return __uint_as_float(f2tf32(__float_as_uint(x)));
}
// scale exponent from raw amax bits: k such that amax*2^-k <= 16384 (4x margin)
__device__ __forceinline__ int amax_k(const unsigned* amaxPtr) {
    float m = __uint_as_float(*amaxPtr);
    int k = 0;
    if (m > 16384.f) k = (int)ceilf(log2f(m * (1.f / 16384.f)));
    if (k < 0) k = 0;
    return k;
}
__device__ __forceinline__ void mma_tf32(float* c, const unsigned* a, const unsigned* b) {
    asm volatile(
        "mma.sync.aligned.m16n8k8.row.col.f32.tf32.tf32.f32 "
        "{%0,%1,%2,%3}, {%4,%5,%6,%7}, {%8,%9}, {%0,%1,%2,%3};\n"
        : "+f"(c[0]), "+f"(c[1]), "+f"(c[2]), "+f"(c[3])
        : "r"(a[0]), "r"(a[1]), "r"(a[2]), "r"(a[3]), "r"(b[0]), "r"(b[1]));
}
__device__ __forceinline__ void mma_f16(float* c, const unsigned* a, const unsigned* b) {
    asm volatile(
        "mma.sync.aligned.m16n8k16.row.col.f32.f16.f16.f32 "
        "{%0,%1,%2,%3}, {%4,%5,%6,%7}, {%8,%9}, {%0,%1,%2,%3};\n"
        : "+f"(c[0]), "+f"(c[1]), "+f"(c[2]), "+f"(c[3])
        : "r"(a[0]), "r"(a[1]), "r"(a[2]), "r"(a[3]), "r"(b[0]), "r"(b[1]));
}
__device__ __forceinline__ void cpa16(void* dst, const void* src, bool pred) {
    unsigned daddr = (unsigned)__cvta_generic_to_shared(dst);
    int sz = pred ? 16 : 0;   // sz=0 -> 16B zero-fill (M/K edges)
    asm volatile("cp.async.cg.shared.global [%0], [%1], 16, %2;\n"
                 :: "r"(daddr), "l"(src), "r"(sz));
}
__device__ __forceinline__ void cpa_commit() {
    asm volatile("cp.async.commit_group;\n");
}
__device__ __forceinline__ void ldsm_x4(unsigned* r, unsigned a) {
    asm volatile("ldmatrix.sync.aligned.m8n8.x4.shared.b16 {%0,%1,%2,%3}, [%4];"
                 : "=r"(r[0]), "=r"(r[1]), "=r"(r[2]), "=r"(r[3]) : "r"(a));
}
__device__ __forceinline__ void ldsm_x4t(unsigned* r, unsigned a) {
    asm volatile("ldmatrix.sync.aligned.m8n8.x4.trans.shared.b16 {%0,%1,%2,%3}, [%4];"
                 : "=r"(r[0]), "=r"(r[1]), "=r"(r[2]), "=r"(r[3]) : "r"(a));
}

// ============================================================================
// fp16 GEMM: C[M,128] += 2^k(amaxIn) * rowscale[m] * (op(A)[M,K] @ B[K,128]),
// atomic split-K into pre-zeroed fp32 C. Optional fused amax of the partial
// contributions scaled by marginMul into amaxOut.
//  TRANS_A=false: A row-major [M,K] fp16 (lda = K)
//  TRANS_A=true : A stored [K,M] fp16, element (m,k) = A[k*lda+m]
// CTA tile 128x128x64, 8 warps, 2 CTAs/SM, 3-stage cp.async.
// kBegin = kOffset + blockIdx.y * kChunk.
// ============================================================================
template <bool TRANS_A>
__global__ void __launch_bounds__(256, 2)
hgemm(const __half* __restrict__ A, const __half* __restrict__ B,
      float* __restrict__ C, int M, int K, int lda,
      const float* __restrict__ rowscale, const unsigned* __restrict__ amaxIn,
      int kChunk, int kOffset,
      unsigned* __restrict__ amaxOut, float marginMul)
{
    constexpr int APITCH = TRANS_A ? (HBM + 8) : (HBK + 8);   // halves
    constexpr int ASZ = TRANS_A ? HBK * (HBM + 8) : HBM * (HBK + 8);
    constexpr int BPITCH = 128 + 8;
    constexpr int BSZ = HBK * BPITCH;
    extern __shared__ char smraw[];
    __half* hsm = (__half*)smraw;

    const int m0 = blockIdx.x * HBM;
    const int kBegin = kOffset + blockIdx.y * kChunk;
    const int kEnd = min(K, kBegin + kChunk);
    if (kBegin >= K) return;
    const int kTiles = (kEnd - kBegin + HBK - 1) / HBK;

    const int tidx = threadIdx.x;
    const int lane = tidx & 31;
    const int g  = lane >> 2;
    const int tg = lane & 3;
    const int wm = (tidx >> 5) & 3;
    const int wn = (tidx >> 7);
    const int lt = lane >> 3;
    const int lr = lane & 7;

    float acc[2][8][4];
#pragma unroll
    for (int mi = 0; mi < 2; mi++)
#pragma unroll
        for (int ni = 0; ni < 8; ni++)
#pragma unroll
            for (int j = 0; j < 4; j++) acc[mi][ni][j] = 0.f;

    auto load_tile = [&](int t, int stage) {
        int kt = kBegin + t * HBK;
        __half* as = hsm + stage * (ASZ + BSZ);
        __half* bs = as + ASZ;
        if (!TRANS_A) {
#pragma unroll
            for (int i = 0; i < 4; i++) {
                int idx = tidx + i * 256;
                int m  = idx >> 3;
                int k8 = (idx & 7) << 3;
                bool p = (m0 + m < M) && (kt + k8 < kEnd);
                const __half* src = p ? &A[(size_t)(m0 + m) * lda + kt + k8] : A;
                cpa16(&as[m * APITCH + k8], src, p);
            }
        } else {
#pragma unroll
            for (int i = 0; i < 4; i++) {
                int idx = tidx + i * 256;
                int k  = idx >> 4;
                int m8 = (idx & 15) << 3;
                int gm = m0 + m8;
                bool p = (gm < M) && (kt + k < kEnd);
                const __half* src = p ? &A[(size_t)(kt + k) * lda + gm] : A;
                cpa16(&as[k * APITCH + m8], src, p);
            }
        }
#pragma unroll
        for (int i = 0; i < 4; i++) {
            int idx = tidx + i * 256;
            int k  = idx >> 4;
            int n8 = (idx & 15) << 3;
            bool p = (kt + k < kEnd);
            const __half* src = p ? &B[(size_t)(kt + k) * 128 + n8] : (const __half*)B;
            cpa16(&bs[k * BPITCH + n8], src, p);
        }
        cpa_commit();
    };

    int pre = kTiles < (HST - 1) ? kTiles : (HST - 1);
    for (int t = 0; t < pre; t++) load_tile(t, t % HST);
    for (int t = pre; t < HST - 1; t++) cpa_commit();

    unsigned smBase = (unsigned)__cvta_generic_to_shared(hsm);

    for (int t = 0; t < kTiles; t++) {
        asm volatile("cp.async.wait_group %0;\n" :: "n"(HST - 2));
        __syncthreads();
        if (t + HST - 1 < kTiles) load_tile(t + HST - 1, (t + HST - 1) % HST);
        else cpa_commit();

        unsigned as_u = smBase + (unsigned)((t % HST) * (ASZ + BSZ) * 2);
        unsigned bs_u = as_u + ASZ * 2;

#pragma unroll
        for (int kk = 0; kk < HBK; kk += 16) {
            unsigned af[2][4];
#pragma unroll
            for (int mi = 0; mi < 2; mi++) {
                int bm = wm * 32 + mi * 16;
                if (!TRANS_A) {
                    unsigned a = as_u + (unsigned)(((bm + (lt & 1) * 8 + lr) * APITCH
                                                   + kk + (lt >> 1) * 8) * 2);
                    ldsm_x4(af[mi], a);
                } else {
                    unsigned a = as_u + (unsigned)(((kk + (lt >> 1) * 8 + lr) * APITCH
                                                   + bm + (lt & 1) * 8) * 2);
                    ldsm_x4t(af[mi], a);
                }
            }
            unsigned bf[8][2];
#pragma unroll
            for (int nj = 0; nj < 4; nj++) {
                unsigned r[4];
                unsigned a = bs_u + (unsigned)(((kk + (lt & 1) * 8 + lr) * BPITCH
                                               + wn * 64 + nj * 16 + (lt >> 1) * 8) * 2);
                ldsm_x4t(r, a);
                bf[2 * nj    ][0] = r[0]; bf[2 * nj    ][1] = r[1];
                bf[2 * nj + 1][0] = r[2]; bf[2 * nj + 1][1] = r[3];
            }
#pragma unroll
            for (int mi = 0; mi < 2; mi++)
#pragma unroll
                for (int ni = 0; ni < 8; ni++)
                    mma_f16(acc[mi][ni], af[mi], bf[ni]);
        }
    }

    // ---- epilogue: atomic split-K; optional fused amax of partials ----
    const float undo = ldexpf(1.f, amax_k(amaxIn));
    float lmax = 0.f;
#pragma unroll
    for (int mi = 0; mi < 2; mi++) {
#pragma unroll
        for (int h = 0; h < 2; h++) {
            int r = m0 + wm * 32 + mi * 16 + g + h * 8;
            if (r >= M) continue;
            float rs = rowscale[r] * undo;
#pragma unroll
            for (int ni = 0; ni < 8; ni++) {
                int cc = wn * 64 + ni * 8 + tg * 2;
                float v0 = acc[mi][ni][h * 2 + 0] * rs;
                float v1 = acc[mi][ni][h * 2 + 1] * rs;
                atomicAdd(&C[(size_t)r * 128 + cc    ], v0);
                atomicAdd(&C[(size_t)r * 128 + cc + 1], v1);
                lmax = fmaxf(lmax, fmaxf(fabsf(v0), fabsf(v1)));
            }
        }
    }
    if (amaxOut) {
        lmax *= marginMul;
#pragma unroll
        for (int o = 16; o; o >>= 1) lmax = fmaxf(lmax, __shfl_xor_sync(~0u, lmax, o));
        if (lane == 0) atomicMax(amaxOut, __float_as_uint(lmax));
    }
}

// ============================================================================
// tf32 GEMM for the small K=128 GEMMs (fp32 out) with FUSED absmax.
// ============================================================================
__global__ void __launch_bounds__(256, 1)
gemm256(const float* __restrict__ A, const float* __restrict__ B,
        float* __restrict__ C, int M,
        const float* __restrict__ bias, const float* __restrict__ rowscale,
        const int* __restrict__ rowsel, int ldbz, int biasz,
        unsigned* __restrict__ amaxOut)
{
    constexpr int K = 128;
    constexpr int APITCH = BK + 4;
    constexpr int ASZ = BM * APITCH;
    constexpr int BPITCH = 128 + 8;
    constexpr int BSZ = BK * BPITCH;
    extern __shared__ char smraw[];
    unsigned* sm = (unsigned*)smraw;

    const int m0 = blockIdx.x * BM;
    const int zt = blockIdx.z;
    B += (size_t)zt * ldbz;
    if (bias) bias += (size_t)zt * biasz;

    const int tidx = threadIdx.x;
    const int lane = tidx & 31;
    const int g  = lane >> 2;
    const int tg = lane & 3;
    const int wm = (tidx >> 5) & 3;
    const int wn = (tidx >> 7);

    float acc[4][8][4];
#pragma unroll
    for (int mi = 0; mi < 4; mi++)
#pragma unroll
        for (int ni = 0; ni < 8; ni++)
#pragma unroll
            for (int j = 0; j < 4; j++) acc[mi][ni][j] = 0.f;

    auto load_tile = [&](int t, int stage) {
        int kt = t * BK;
        unsigned* as = sm + stage * (ASZ + BSZ);
        unsigned* bs = as + ASZ;
#pragma unroll
        for (int i = 0; i < 8; i++) {
            int idx = tidx + i * 256;
            int m  = idx >> 3;
            int k4 = (idx & 7) << 2;
            bool p = (m0 + m < M);
            const float* src = p ? &A[(size_t)(m0 + m) * K + kt + k4] : A;
            cpa16(&as[m * APITCH + k4], src, p);
        }
#pragma unroll
        for (int i = 0; i < 4; i++) {
            int idx = tidx + i * 256;
            int k  = idx >> 5;
            int n4 = (idx & 31) << 2;
            cpa16(&bs[k * BPITCH + n4], &B[(size_t)(kt + k) * 128 + n4], true);
        }
        cpa_commit();
    };

    const int kTiles = K / BK;
    int pre = kTiles < (STAGES - 1) ? kTiles : (STAGES - 1);
    for (int t = 0; t < pre; t++) load_tile(t, t % STAGES);
    for (int t = pre; t < STAGES - 1; t++) cpa_commit();

    for (int t = 0; t < kTiles; t++) {
        asm volatile("cp.async.wait_group %0;\n" :: "n"(STAGES - 2));
        __syncthreads();
        if (t + STAGES - 1 < kTiles) load_tile(t + STAGES - 1, (t + STAGES - 1) % STAGES);
        else cpa_commit();

        const unsigned* as = sm + (t % STAGES) * (ASZ + BSZ);
        const unsigned* bs = as + ASZ;

#pragma unroll
        for (int kk = 0; kk < BK; kk += 8) {
            unsigned af[4][4];
#pragma unroll
            for (int mi = 0; mi < 4; mi++) {
                int bm = wm * 64 + mi * 16;
                af[mi][0] = f2tf32(as[(bm + g    ) * APITCH + kk + tg    ]);
                af[mi][1] = f2tf32(as[(bm + g + 8) * APITCH + kk + tg    ]);
                af[mi][2] = f2tf32(as[(bm + g    ) * APITCH + kk + tg + 4]);
                af[mi][3] = f2tf32(as[(bm + g + 8) * APITCH + kk + tg + 4]);
            }
            unsigned bf[8][2];
#pragma unroll
            for (int ni = 0; ni < 8; ni++) {
                int bn = wn * 64 + ni * 8;
                bf[ni][0] = bs[(kk + tg    ) * BPITCH + bn + g];
                bf[ni][1] = bs[(kk + tg + 4) * BPITCH + bn + g];
            }
#pragma unroll
            for (int mi = 0; mi < 4; mi++)
#pragma unroll
                for (int ni = 0; ni < 8; ni++)
                    mma_tf32(acc[mi][ni], af[mi], bf[ni]);
        }
    }

    float lmax = 0.f;
#pragma unroll
    for (int mi = 0; mi < 4; mi++) {
#pragma unroll
        for (int h = 0; h < 2; h++) {
            int r = m0 + wm * 64 + mi * 16 + g + h * 8;
            if (r >= M) continue;
            if (rowsel && rowsel[r] != zt) continue;
            float rs = rowscale ? rowscale[r] : 1.f;
#pragma unroll
            for (int ni = 0; ni < 8; ni++) {
                int cc = wn * 64 + ni * 8 + tg * 2;
                float v0 = acc[mi][ni][h * 2 + 0];
                float v1 = acc[mi][ni][h * 2 + 1];
                if (bias) { v0 += bias[cc]; v1 += bias[cc + 1]; }
                v0 *= rs; v1 *= rs;
                C[(size_t)r * 128 + cc    ] = v0;
                C[(size_t)r * 128 + cc + 1] = v1;
                lmax = fmaxf(lmax, fmaxf(fabsf(v0), fabsf(v1)));
            }
        }
    }
    if (amaxOut) {
#pragma unroll
        for (int o = 16; o; o >>= 1) lmax = fmaxf(lmax, __shfl_xor_sync(~0u, lmax, o));
        if (lane == 0) atomicMax(amaxOut, __float_as_uint(lmax));
    }
}

// ---------------- small kernels ----------------
__global__ void zero_kernel(float* __restrict__ p, int n) {
    int i = blockIdx.x * blockDim.x + threadIdx.x;
    if (i < n) p[i] = 0.f;
}
__global__ void reset_amax4(unsigned* slot) {
    slot[0] = 0u; slot[1] = 0u; slot[2] = 0u; slot[3] = 0u;
}

// fp32 -> fp16 (RN), scaled by 2^-k(amax) (amaxPtr null => scale 1)
__global__ void f2h_dyn(__half* __restrict__ dst, const float* __restrict__ src,
                        long long n8, const unsigned* __restrict__ amaxPtr) {
    float s = amaxPtr ? ldexpf(1.f, -amax_k(amaxPtr)) : 1.f;
    long long i = (long long)blockIdx.x * blockDim.x + threadIdx.x;
    if (i < n8) {
        float4 a = ((const float4*)src)[2 * i];
        float4 b = ((const float4*)src)[2 * i + 1];
        __half2 h[4];
        h[0] = __floats2half2_rn(a.x * s, a.y * s);
        h[1] = __floats2half2_rn(a.z * s, a.w * s);
        h[2] = __floats2half2_rn(b.x * s, b.y * s);
        h[3] = __floats2half2_rn(b.z * s, b.w * s);
        ((uint4*)dst)[i] = *(uint4*)h;
    }
}

__global__ void round_tf32_kernel(float* __restrict__ dst, const float* __restrict__ src, int n4) {
    int i = blockIdx.x * blockDim.x + threadIdx.x;
    if (i < n4) {
        float4 v = ((const float4*)src)[i];
        v.x = roundtf(v.x); v.y = roundtf(v.y);
        v.z = roundtf(v.z); v.w = roundtf(v.w);
        ((float4*)dst)[i] = v;
    }
}

__global__ void fusion_kernel(const float* __restrict__ fw,
                              const float* __restrict__ X0,
                              const float* __restrict__ X1,
                              const float* __restrict__ X2,
                              float* __restrict__ out, int n) {
    float f0 = fw[0], f1 = fw[1], f2 = fw[2];
    float mx = fmaxf(f0, fmaxf(f1, f2));
    float e0 = expf(f0 - mx), e1 = expf(f1 - mx), e2 = expf(f2 - mx);
    float inv = 1.f / (e0 + e1 + e2);
    float w0 = e0 * inv, w1 = e1 * inv, w2 = e2 * inv;
    int i = blockIdx.x * blockDim.x + threadIdx.x;
    if (i < n) out[i] = w0 * X0[i] + w1 * X1[i] + w2 * X2[i];
}

static inline int chunk64(int K, int S) {
    int tiles = (K + HBK - 1) / HBK;
    int per = (tiles + S - 1) / S;
    return per * HBK;
}

extern "C" void kernel_launch(void* const* d_in, const int* in_sizes, int n_in,
                              void* d_out, int out_size) {
    const float* emb = (const float*)d_in[0];
    const float* Wt  = (const float*)d_in[1];
    const float* bt  = (const float*)d_in[2];
    const float* W1  = (const float*)d_in[3];
    const float* b1  = (const float*)d_in[4];
    const float* W2  = (const float*)d_in[5];
    const float* b2  = (const float*)d_in[6];
    const float* fw  = (const float*)d_in[7];
    const float* H   = (const float*)d_in[8];
    const float* dv  = (const float*)d_in[9];
    const float* de  = (const float*)d_in[10];
    const int*   tid = (const int*)d_in[11];

    const int D = in_sizes[4];          // 128
    const int N = in_sizes[9];          // 20000
    const int E = in_sizes[10];         // 8000
    const int T = in_sizes[2] / D;      // 5

    float* buf = nullptr;
    cudaGetSymbolAddress((void**)&buf, g_buf);
    __half* hb = nullptr;
    cudaGetSymbolAddress((void**)&hb, g_hbuf);
    unsigned* sc = nullptr;
    cudaGetSymbolAddress((void**)&sc, g_sc);

    size_t nd = (size_t)N * D, ed = (size_t)E * D, ne = (size_t)N * E;
    float* X0  = buf;
    float* X1  = X0 + nd;
    float* X2  = X1 + nd;
    float* Yf  = X2 + nd;
    float* Mm0 = Yf + nd;
    float* Mm1 = Mm0 + ed;
    float* Wtr = Mm1 + ed;
    float* W1r = Wtr + (size_t)T * D * D;
    float* W2r = W1r + (size_t)D * D;
    __half* Hh  = hb;
    __half* Yh  = Hh + ne;
    __half* Mmh = Yh + nd;

    unsigned* amaxY0 = sc + 0;
    unsigned* amaxY1 = sc + 1;
    unsigned* amaxM0 = sc + 2;
    unsigned* amaxM1 = sc + 3;

    const int smemG  = STAGES * (BM * (BK + 4) + BK * (128 + 8)) * 4;
    const int smemHT = HST * (HBK * (HBM + 8) + HBK * (128 + 8)) * 2;
    const int smemHN = HST * (HBM * (HBK + 8) + HBK * (128 + 8)) * 2;

    static cudaStream_t s2 = nullptr;
    static cudaEvent_t evFork = nullptr, evSide = nullptr, evH1 = nullptr, evH2 = nullptr;
    static bool attr_done = false;
    if (!attr_done) {
        cudaFuncSetAttribute(gemm256,      cudaFuncAttributeMaxDynamicSharedMemorySize, smemG);
        cudaFuncSetAttribute(hgemm<true>,  cudaFuncAttributeMaxDynamicSharedMemorySize, smemHT);
        cudaFuncSetAttribute(hgemm<false>, cudaFuncAttributeMaxDynamicSharedMemorySize, smemHN);
        cudaStreamCreateWithFlags(&s2, cudaStreamNonBlocking);
        cudaEventCreateWithFlags(&evFork, cudaEventDisableTiming);
        cudaEventCreateWithFlags(&evSide, cudaEventDisableTiming);
        cudaEventCreateWithFlags(&evH1, cudaEventDisableTiming);
        cudaEventCreateWithFlags(&evH2, cudaEventDisableTiming);
        attr_done = true;
    }

    dim3 blk(256);
    int mt_n  = (N + BM - 1) / BM;      // 79 (tf32)
    int ht_n  = (N + HBM - 1) / HBM;    // 157
    int ht_e  = (E + HBM - 1) / HBM;    // 63
    const int S1 = 9;                   // trans split-K: 567 CTAs
    const int S2 = 7;                   // non-trans: 1099 CTAs
    const int S1A = 5;                  // first gated sub-launch (splits 0..4)
    int ch1 = chunk64(N, S1);           // 2240
    int ch2 = chunk64(E, S2);           // 1152
    int zt_ = 256;
    int w_n4 = D * D / 4;
    const float margin1 = (float)S1;    // split-count bound for fused Mm amax

    // ---- fork: ALL prep + chunked H conversion on side stream ----
    cudaEventRecord(evFork, 0);
    cudaStreamWaitEvent(s2, evFork, 0);
    {
        reset_amax4<<<1, 1, 0, s2>>>(sc);
        round_tf32_kernel<<<(w_n4 + 255) / 256, 256, 0, s2>>>(W1r, W1, w_n4);
        round_tf32_kernel<<<(w_n4 + 255) / 256, 256, 0, s2>>>(W2r, W2, w_n4);
        zero_kernel<<<(int)((ed + zt_ - 1) / zt_), zt_, 0, s2>>>(Mm0, (int)ed);
        zero_kernel<<<(int)((ed + zt_ - 1) / zt_), zt_, 0, s2>>>(Mm1, (int)ed);
        zero_kernel<<<(int)((nd + zt_ - 1) / zt_), zt_, 0, s2>>>(X1, (int)nd);
        zero_kernel<<<(int)((nd + zt_ - 1) / zt_), zt_, 0, s2>>>(X2, (int)nd);
        cudaEventRecord(evSide, s2);
        // H conversion in two chunks (rows [0,S1A*ch1), [S1A*ch1, N))
        long long rowsA = (long long)S1A * ch1;            // 11200
        long long nA8 = rowsA * E / 8;
        long long nB8 = ((long long)N - rowsA) * E / 8;
        f2h_dyn<<<(int)((nA8 + 255) / 256), 256, 0, s2>>>(Hh, H, nA8, nullptr);
        cudaEventRecord(evH1, s2);
        f2h_dyn<<<(int)((nB8 + 255) / 256), 256, 0, s2>>>(
            Hh + rowsA * E, H + rowsA * E, nB8, nullptr);
        cudaEventRecord(evH2, s2);
    }

    // ---- main chain ----
    int wt_n4 = T * D * D / 4;
    round_tf32_kernel<<<(wt_n4 + 255) / 256, 256>>>(Wtr, Wt, wt_n4);

    gemm256<<<dim3(mt_n, 1, T), blk, smemG>>>(
        emb, Wtr, X0, N, bt, nullptr, tid, D * D, D, nullptr);

    // join prep (W1r, zeros, amax resets)
    cudaStreamWaitEvent(0, evSide, 0);

    // ======== layer 1 ========
    gemm256<<<dim3(mt_n, 1, 1), blk, smemG>>>(
        X0, W1r, Yf, N, b1, dv, nullptr, 0, 0, amaxY0);
    f2h_dyn<<<(int)((nd / 8 + 255) / 256), 256>>>(Yh, Yf, (long long)(nd / 8), amaxY0);
    // trans hgemm gated per H chunk: splits 0..4 then 5..8
    cudaStreamWaitEvent(0, evH1, 0);
    hgemm<true><<<dim3(ht_e, S1A, 1), blk, smemHT>>>(
        Hh, Yh, Mm0, E, N, E, de, amaxY0, ch1, 0, amaxM0, margin1);
    cudaStreamWaitEvent(0, evH2, 0);
    hgemm<true><<<dim3(ht_e, S1 - S1A, 1), blk, smemHT>>>(
        Hh, Yh, Mm0, E, N, E, de, amaxY0, ch1, S1A * ch1, amaxM0, margin1);
    f2h_dyn<<<(int)((ed / 8 + 255) / 256), 256>>>(Mmh, Mm0, (long long)(ed / 8), amaxM0);
    hgemm<false><<<dim3(ht_n, S2, 1), blk, smemHN>>>(
        Hh, Mmh, X1, N, E, E, dv, amaxM0, ch2, 0, nullptr, 1.f);

    // ======== layer 2 ========
    gemm256<<<dim3(mt_n, 1, 1), blk, smemG>>>(
        X1, W2r, Yf, N, b2, dv, nullptr, 0, 0, amaxY1);
    f2h_dyn<<<(int)((nd / 8 + 255) / 256), 256>>>(Yh, Yf, (long long)(nd / 8), amaxY1);
    hgemm<true><<<dim3(ht_e, S1, 1), blk, smemHT>>>(
        Hh, Yh, Mm1, E, N, E, de, amaxY1, ch1, 0, amaxM1, margin1);
    f2h_dyn<<<(int)((ed / 8 + 255) / 256), 256>>>(Mmh, Mm1, (long long)(ed / 8), amaxM1);
    hgemm<false><<<dim3(ht_n, S2, 1), blk, smemHN>>>(
        Hh, Mmh, X2, N, E, E, dv, amaxM1, ch2, 0, nullptr, 1.f);

    // ---- fusion ----
    fusion_kernel<<<(int)((nd + zt_ - 1) / zt_), zt_>>>(
        fw, X0, X1, X2, (float*)d_out, (int)nd);
}

// round 16
// speedup vs baseline: 1.0376x; 1.0376x over previous
#include <cuda_runtime.h>
#include <cuda_fp16.h>
#include <math.h>

// ----------------------------------------------------------------------------
// HyperGraphModel on GB300.
//  - 4 big H-GEMMs in fp16 (HMMA m16n8k16, fp32 accum, ldmatrix fragments,
//    3-stage BK=64 cp.async pipeline, ONE barrier per k-tile, 2 CTAs/SM).
//  - Dynamic pow-2 scaling: amax fused into producing epilogues. For split-K
//    outputs (Mm) the epilogue records max|partial|*S — a provable upper
//    bound on the true amax (|sum| <= S*max|partial|); overshoot <=S only
//    costs exponent headroom, not relative precision.
//  - H->fp16 conversion as ONE launch on a side stream (round-15 chunked
//    variant regressed: 63-tile columns can't pack whole waves when split).
//  - All scratch prep (resets/zeros/weight rounding) rides the side stream.
//  NOTE: tcgen05 unavailable — ptxas here targets sm_103 (no 'a'), verified
//  round 12.
// ----------------------------------------------------------------------------

#define BM 256           // tf32 kernel M tile
#define BK 32            // tf32 kernel k-tile
#define HBM 128          // fp16 kernel M tile (2 CTAs/SM)
#define HBK 64           // fp16 kernel k-tile
#define STAGES 3         // tf32 stages
#define HST 3            // fp16 stages

// fp32 scratch: X0,X1,X2,Yf (4*N*D) + Mm0 (E*D) + Mm1 (E*D) + Wtr + W1r + W2r
__device__ float g_buf[12500000];
// fp16 scratch: Hh (N*E) + Yh (N*D) + Mmh (E*D)
__device__ __align__(256) __half g_hbuf[163600000];
// scale slots: [0]=amaxY0 [1]=amaxY1 [2]=amaxM0 [3]=amaxM1
__device__ unsigned g_sc[8];

// ---------------- common helpers ----------------
__device__ __forceinline__ unsigned f2tf32(unsigned x) {
    unsigned r;
    asm("cvt.rna.tf32.f32 %0, %1;" : "=r"(r) : "r"(x));
    return r;
}
__device__ __forceinline__ float roundtf(float x) {
    return __uint_as_float(f2tf32(__float_as_uint(x)));
}
// scale exponent from raw amax bits: k such that amax*2^-k <= 16384 (4x margin)
__device__ __forceinline__ int amax_k(const unsigned* amaxPtr) {
    float m = __uint_as_float(*amaxPtr);
    int k = 0;
    if (m > 16384.f) k = (int)ceilf(log2f(m * (1.f / 16384.f)));
    if (k < 0) k = 0;
    return k;
}
__device__ __forceinline__ void mma_tf32(float* c, const unsigned* a, const unsigned* b) {
    asm volatile(
        "mma.sync.aligned.m16n8k8.row.col.f32.tf32.tf32.f32 "
        "{%0,%1,%2,%3}, {%4,%5,%6,%7}, {%8,%9}, {%0,%1,%2,%3};\n"
        : "+f"(c[0]), "+f"(c[1]), "+f"(c[2]), "+f"(c[3])
        : "r"(a[0]), "r"(a[1]), "r"(a[2]), "r"(a[3]), "r"(b[0]), "r"(b[1]));
}
__device__ __forceinline__ void mma_f16(float* c, const unsigned* a, const unsigned* b) {
    asm volatile(
        "mma.sync.aligned.m16n8k16.row.col.f32.f16.f16.f32 "
        "{%0,%1,%2,%3}, {%4,%5,%6,%7}, {%8,%9}, {%0,%1,%2,%3};\n"
        : "+f"(c[0]), "+f"(c[1]), "+f"(c[2]), "+f"(c[3])
        : "r"(a[0]), "r"(a[1]), "r"(a[2]), "r"(a[3]), "r"(b[0]), "r"(b[1]));
}
__device__ __forceinline__ void cpa16(void* dst, const void* src, bool pred) {
    unsigned daddr = (unsigned)__cvta_generic_to_shared(dst);
    int sz = pred ? 16 : 0;   // sz=0 -> 16B zero-fill (M/K edges)
    asm volatile("cp.async.cg.shared.global [%0], [%1], 16, %2;\n"
                 :: "r"(daddr), "l"(src), "r"(sz));
}
__device__ __forceinline__ void cpa_commit() {
    asm volatile("cp.async.commit_group;\n");
}
__device__ __forceinline__ void ldsm_x4(unsigned* r, unsigned a) {
    asm volatile("ldmatrix.sync.aligned.m8n8.x4.shared.b16 {%0,%1,%2,%3}, [%4];"
                 : "=r"(r[0]), "=r"(r[1]), "=r"(r[2]), "=r"(r[3]) : "r"(a));
}
__device__ __forceinline__ void ldsm_x4t(unsigned* r, unsigned a) {
    asm volatile("ldmatrix.sync.aligned.m8n8.x4.trans.shared.b16 {%0,%1,%2,%3}, [%4];"
                 : "=r"(r[0]), "=r"(r[1]), "=r"(r[2]), "=r"(r[3]) : "r"(a));
}

// ============================================================================
// fp16 GEMM: C[M,128] += 2^k(amaxIn) * rowscale[m] * (op(A)[M,K] @ B[K,128]),
// atomic split-K into pre-zeroed fp32 C. Optional fused amax of the partial
// contributions scaled by marginMul into amaxOut.
//  TRANS_A=false: A row-major [M,K] fp16 (lda = K)
//  TRANS_A=true : A stored [K,M] fp16, element (m,k) = A[k*lda+m]
// CTA tile 128x128x64, 8 warps, 2 CTAs/SM, 3-stage cp.async.
// ============================================================================
template <bool TRANS_A>
__global__ void __launch_bounds__(256, 2)
hgemm(const __half* __restrict__ A, const __half* __restrict__ B,
      float* __restrict__ C, int M, int K, int lda,
      const float* __restrict__ rowscale, const unsigned* __restrict__ amaxIn,
      int kChunk, unsigned* __restrict__ amaxOut, float marginMul)
{
    constexpr int APITCH = TRANS_A ? (HBM + 8) : (HBK + 8);   // halves
    constexpr int ASZ = TRANS_A ? HBK * (HBM + 8) : HBM * (HBK + 8);
    constexpr int BPITCH = 128 + 8;
    constexpr int BSZ = HBK * BPITCH;
    extern __shared__ char smraw[];
    __half* hsm = (__half*)smraw;

    const int m0 = blockIdx.x * HBM;
    const int kBegin = blockIdx.y * kChunk;
    const int kEnd = min(K, kBegin + kChunk);
    if (kBegin >= K) return;
    const int kTiles = (kEnd - kBegin + HBK - 1) / HBK;

    const int tidx = threadIdx.x;
    const int lane = tidx & 31;
    const int g  = lane >> 2;
    const int tg = lane & 3;
    const int wm = (tidx >> 5) & 3;
    const int wn = (tidx >> 7);
    const int lt = lane >> 3;
    const int lr = lane & 7;

    float acc[2][8][4];
#pragma unroll
    for (int mi = 0; mi < 2; mi++)
#pragma unroll
        for (int ni = 0; ni < 8; ni++)
#pragma unroll
            for (int j = 0; j < 4; j++) acc[mi][ni][j] = 0.f;

    auto load_tile = [&](int t, int stage) {
        int kt = kBegin + t * HBK;
        __half* as = hsm + stage * (ASZ + BSZ);
        __half* bs = as + ASZ;
        if (!TRANS_A) {
#pragma unroll
            for (int i = 0; i < 4; i++) {
                int idx = tidx + i * 256;
                int m  = idx >> 3;
                int k8 = (idx & 7) << 3;
                bool p = (m0 + m < M) && (kt + k8 < kEnd);
                const __half* src = p ? &A[(size_t)(m0 + m) * lda + kt + k8] : A;
                cpa16(&as[m * APITCH + k8], src, p);
            }
        } else {
#pragma unroll
            for (int i = 0; i < 4; i++) {
                int idx = tidx + i * 256;
                int k  = idx >> 4;
                int m8 = (idx & 15) << 3;
                int gm = m0 + m8;
                bool p = (gm < M) && (kt + k < kEnd);
                const __half* src = p ? &A[(size_t)(kt + k) * lda + gm] : A;
                cpa16(&as[k * APITCH + m8], src, p);
            }
        }
#pragma unroll
        for (int i = 0; i < 4; i++) {
            int idx = tidx + i * 256;
            int k  = idx >> 4;
            int n8 = (idx & 15) << 3;
            bool p = (kt + k < kEnd);
            const __half* src = p ? &B[(size_t)(kt + k) * 128 + n8] : (const __half*)B;
            cpa16(&bs[k * BPITCH + n8], src, p);
        }
        cpa_commit();
    };

    int pre = kTiles < (HST - 1) ? kTiles : (HST - 1);
    for (int t = 0; t < pre; t++) load_tile(t, t % HST);
    for (int t = pre; t < HST - 1; t++) cpa_commit();

    unsigned smBase = (unsigned)__cvta_generic_to_shared(hsm);

    for (int t = 0; t < kTiles; t++) {
        asm volatile("cp.async.wait_group %0;\n" :: "n"(HST - 2));
        __syncthreads();
        if (t + HST - 1 < kTiles) load_tile(t + HST - 1, (t + HST - 1) % HST);
        else cpa_commit();

        unsigned as_u = smBase + (unsigned)((t % HST) * (ASZ + BSZ) * 2);
        unsigned bs_u = as_u + ASZ * 2;

#pragma unroll
        for (int kk = 0; kk < HBK; kk += 16) {
            unsigned af[2][4];
#pragma unroll
            for (int mi = 0; mi < 2; mi++) {
                int bm = wm * 32 + mi * 16;
                if (!TRANS_A) {
                    unsigned a = as_u + (unsigned)(((bm + (lt & 1) * 8 + lr) * APITCH
                                                   + kk + (lt >> 1) * 8) * 2);
                    ldsm_x4(af[mi], a);
                } else {
                    unsigned a = as_u + (unsigned)(((kk + (lt >> 1) * 8 + lr) * APITCH
                                                   + bm + (lt & 1) * 8) * 2);
                    ldsm_x4t(af[mi], a);
                }
            }
            unsigned bf[8][2];
#pragma unroll
            for (int nj = 0; nj < 4; nj++) {
                unsigned r[4];
                unsigned a = bs_u + (unsigned)(((kk + (lt & 1) * 8 + lr) * BPITCH
                                               + wn * 64 + nj * 16 + (lt >> 1) * 8) * 2);
                ldsm_x4t(r, a);
                bf[2 * nj    ][0] = r[0]; bf[2 * nj    ][1] = r[1];
                bf[2 * nj + 1][0] = r[2]; bf[2 * nj + 1][1] = r[3];
            }
#pragma unroll
            for (int mi = 0; mi < 2; mi++)
#pragma unroll
                for (int ni = 0; ni < 8; ni++)
                    mma_f16(acc[mi][ni], af[mi], bf[ni]);
        }
    }

    // ---- epilogue: atomic split-K; optional fused amax of partials ----
    const float undo = ldexpf(1.f, amax_k(amaxIn));
    float lmax = 0.f;
#pragma unroll
    for (int mi = 0; mi < 2; mi++) {
#pragma unroll
        for (int h = 0; h < 2; h++) {
            int r = m0 + wm * 32 + mi * 16 + g + h * 8;
            if (r >= M) continue;
            float rs = rowscale[r] * undo;
#pragma unroll
            for (int ni = 0; ni < 8; ni++) {
                int cc = wn * 64 + ni * 8 + tg * 2;
                float v0 = acc[mi][ni][h * 2 + 0] * rs;
                float v1 = acc[mi][ni][h * 2 + 1] * rs;
                atomicAdd(&C[(size_t)r * 128 + cc    ], v0);
                atomicAdd(&C[(size_t)r * 128 + cc + 1], v1);
                lmax = fmaxf(lmax, fmaxf(fabsf(v0), fabsf(v1)));
            }
        }
    }
    if (amaxOut) {
        lmax *= marginMul;
#pragma unroll
        for (int o = 16; o; o >>= 1) lmax = fmaxf(lmax, __shfl_xor_sync(~0u, lmax, o));
        if (lane == 0) atomicMax(amaxOut, __float_as_uint(lmax));
    }
}

// ============================================================================
// tf32 GEMM for the small K=128 GEMMs (fp32 out) with FUSED absmax.
// ============================================================================
__global__ void __launch_bounds__(256, 1)
gemm256(const float* __restrict__ A, const float* __restrict__ B,
        float* __restrict__ C, int M,
        const float* __restrict__ bias, const float* __restrict__ rowscale,
        const int* __restrict__ rowsel, int ldbz, int biasz,
        unsigned* __restrict__ amaxOut)
{
    constexpr int K = 128;
    constexpr int APITCH = BK + 4;
    constexpr int ASZ = BM * APITCH;
    constexpr int BPITCH = 128 + 8;
    constexpr int BSZ = BK * BPITCH;
    extern __shared__ char smraw[];
    unsigned* sm = (unsigned*)smraw;

    const int m0 = blockIdx.x * BM;
    const int zt = blockIdx.z;
    B += (size_t)zt * ldbz;
    if (bias) bias += (size_t)zt * biasz;

    const int tidx = threadIdx.x;
    const int lane = tidx & 31;
    const int g  = lane >> 2;
    const int tg = lane & 3;
    const int wm = (tidx >> 5) & 3;
    const int wn = (tidx >> 7);

    float acc[4][8][4];
#pragma unroll
    for (int mi = 0; mi < 4; mi++)
#pragma unroll
        for (int ni = 0; ni < 8; ni++)
#pragma unroll
            for (int j = 0; j < 4; j++) acc[mi][ni][j] = 0.f;

    auto load_tile = [&](int t, int stage) {
        int kt = t * BK;
        unsigned* as = sm + stage * (ASZ + BSZ);
        unsigned* bs = as + ASZ;
#pragma unroll
        for (int i = 0; i < 8; i++) {
            int idx = tidx + i * 256;
            int m  = idx >> 3;
            int k4 = (idx & 7) << 2;
            bool p = (m0 + m < M);
            const float* src = p ? &A[(size_t)(m0 + m) * K + kt + k4] : A;
            cpa16(&as[m * APITCH + k4], src, p);
        }
#pragma unroll
        for (int i = 0; i < 4; i++) {
            int idx = tidx + i * 256;
            int k  = idx >> 5;
            int n4 = (idx & 31) << 2;
            cpa16(&bs[k * BPITCH + n4], &B[(size_t)(kt + k) * 128 + n4], true);
        }
        cpa_commit();
    };

    const int kTiles = K / BK;
    int pre = kTiles < (STAGES - 1) ? kTiles : (STAGES - 1);
    for (int t = 0; t < pre; t++) load_tile(t, t % STAGES);
    for (int t = pre; t < STAGES - 1; t++) cpa_commit();

    for (int t = 0; t < kTiles; t++) {
        asm volatile("cp.async.wait_group %0;\n" :: "n"(STAGES - 2));
        __syncthreads();
        if (t + STAGES - 1 < kTiles) load_tile(t + STAGES - 1, (t + STAGES - 1) % STAGES);
        else cpa_commit();

        const unsigned* as = sm + (t % STAGES) * (ASZ + BSZ);
        const unsigned* bs = as + ASZ;

#pragma unroll
        for (int kk = 0; kk < BK; kk += 8) {
            unsigned af[4][4];
#pragma unroll
            for (int mi = 0; mi < 4; mi++) {
                int bm = wm * 64 + mi * 16;
                af[mi][0] = f2tf32(as[(bm + g    ) * APITCH + kk + tg    ]);
                af[mi][1] = f2tf32(as[(bm + g + 8) * APITCH + kk + tg    ]);
                af[mi][2] = f2tf32(as[(bm + g    ) * APITCH + kk + tg + 4]);
                af[mi][3] = f2tf32(as[(bm + g + 8) * APITCH + kk + tg + 4]);
            }
            unsigned bf[8][2];
#pragma unroll
            for (int ni = 0; ni < 8; ni++) {
                int bn = wn * 64 + ni * 8;
                bf[ni][0] = bs[(kk + tg    ) * BPITCH + bn + g];
                bf[ni][1] = bs[(kk + tg + 4) * BPITCH + bn + g];
            }
#pragma unroll
            for (int mi = 0; mi < 4; mi++)
#pragma unroll
                for (int ni = 0; ni < 8; ni++)
                    mma_tf32(acc[mi][ni], af[mi], bf[ni]);
        }
    }

    float lmax = 0.f;
#pragma unroll
    for (int mi = 0; mi < 4; mi++) {
#pragma unroll
        for (int h = 0; h < 2; h++) {
            int r = m0 + wm * 64 + mi * 16 + g + h * 8;
            if (r >= M) continue;
            if (rowsel && rowsel[r] != zt) continue;
            float rs = rowscale ? rowscale[r] : 1.f;
#pragma unroll
            for (int ni = 0; ni < 8; ni++) {
                int cc = wn * 64 + ni * 8 + tg * 2;
                float v0 = acc[mi][ni][h * 2 + 0];
                float v1 = acc[mi][ni][h * 2 + 1];
                if (bias) { v0 += bias[cc]; v1 += bias[cc + 1]; }
                v0 *= rs; v1 *= rs;
                C[(size_t)r * 128 + cc    ] = v0;
                C[(size_t)r * 128 + cc + 1] = v1;
                lmax = fmaxf(lmax, fmaxf(fabsf(v0), fabsf(v1)));
            }
        }
    }
    if (amaxOut) {
#pragma unroll
        for (int o = 16; o; o >>= 1) lmax = fmaxf(lmax, __shfl_xor_sync(~0u, lmax, o));
        if (lane == 0) atomicMax(amaxOut, __float_as_uint(lmax));
    }
}

// ---------------- small kernels ----------------
__global__ void zero_kernel(float* __restrict__ p, int n) {
    int i = blockIdx.x * blockDim.x + threadIdx.x;
    if (i < n) p[i] = 0.f;
}
__global__ void reset_amax4(unsigned* slot) {
    slot[0] = 0u; slot[1] = 0u; slot[2] = 0u; slot[3] = 0u;
}

// fp32 -> fp16 (RN), scaled by 2^-k(amax) (amaxPtr null => scale 1)
__global__ void f2h_dyn(__half* __restrict__ dst, const float* __restrict__ src,
                        long long n8, const unsigned* __restrict__ amaxPtr) {
    float s = amaxPtr ? ldexpf(1.f, -amax_k(amaxPtr)) : 1.f;
    long long i = (long long)blockIdx.x * blockDim.x + threadIdx.x;
    if (i < n8) {
        float4 a = ((const float4*)src)[2 * i];
        float4 b = ((const float4*)src)[2 * i + 1];
        __half2 h[4];
        h[0] = __floats2half2_rn(a.x * s, a.y * s);
        h[1] = __floats2half2_rn(a.z * s, a.w * s);
        h[2] = __floats2half2_rn(b.x * s, b.y * s);
        h[3] = __floats2half2_rn(b.z * s, b.w * s);
        ((uint4*)dst)[i] = *(uint4*)h;
    }
}

__global__ void round_tf32_kernel(float* __restrict__ dst, const float* __restrict__ src, int n4) {
    int i = blockIdx.x * blockDim.x + threadIdx.x;
    if (i < n4) {
        float4 v = ((const float4*)src)[i];
        v.x = roundtf(v.x); v.y = roundtf(v.y);
        v.z = roundtf(v.z); v.w = roundtf(v.w);
        ((float4*)dst)[i] = v;
    }
}

__global__ void fusion_kernel(const float* __restrict__ fw,
                              const float* __restrict__ X0,
                              const float* __restrict__ X1,
                              const float* __restrict__ X2,
                              float* __restrict__ out, int n) {
    float f0 = fw[0], f1 = fw[1], f2 = fw[2];
    float mx = fmaxf(f0, fmaxf(f1, f2));
    float e0 = expf(f0 - mx), e1 = expf(f1 - mx), e2 = expf(f2 - mx);
    float inv = 1.f / (e0 + e1 + e2);
    float w0 = e0 * inv, w1 = e1 * inv, w2 = e2 * inv;
    int i = blockIdx.x * blockDim.x + threadIdx.x;
    if (i < n) out[i] = w0 * X0[i] + w1 * X1[i] + w2 * X2[i];
}

static inline int chunk64(int K, int S) {
    int tiles = (K + HBK - 1) / HBK;
    int per = (tiles + S - 1) / S;
    return per * HBK;
}

extern "C" void kernel_launch(void* const* d_in, const int* in_sizes, int n_in,
                              void* d_out, int out_size) {
    const float* emb = (const float*)d_in[0];
    const float* Wt  = (const float*)d_in[1];
    const float* bt  = (const float*)d_in[2];
    const float* W1  = (const float*)d_in[3];
    const float* b1  = (const float*)d_in[4];
    const float* W2  = (const float*)d_in[5];
    const float* b2  = (const float*)d_in[6];
    const float* fw  = (const float*)d_in[7];
    const float* H   = (const float*)d_in[8];
    const float* dv  = (const float*)d_in[9];
    const float* de  = (const float*)d_in[10];
    const int*   tid = (const int*)d_in[11];

    const int D = in_sizes[4];          // 128
    const int N = in_sizes[9];          // 20000
    const int E = in_sizes[10];         // 8000
    const int T = in_sizes[2] / D;      // 5

    float* buf = nullptr;
    cudaGetSymbolAddress((void**)&buf, g_buf);
    __half* hb = nullptr;
    cudaGetSymbolAddress((void**)&hb, g_hbuf);
    unsigned* sc = nullptr;
    cudaGetSymbolAddress((void**)&sc, g_sc);

    size_t nd = (size_t)N * D, ed = (size_t)E * D, ne = (size_t)N * E;
    float* X0  = buf;
    float* X1  = X0 + nd;
    float* X2  = X1 + nd;
    float* Yf  = X2 + nd;
    float* Mm0 = Yf + nd;
    float* Mm1 = Mm0 + ed;
    float* Wtr = Mm1 + ed;
    float* W1r = Wtr + (size_t)T * D * D;
    float* W2r = W1r + (size_t)D * D;
    __half* Hh  = hb;
    __half* Yh  = Hh + ne;
    __half* Mmh = Yh + nd;

    unsigned* amaxY0 = sc + 0;
    unsigned* amaxY1 = sc + 1;
    unsigned* amaxM0 = sc + 2;
    unsigned* amaxM1 = sc + 3;

    const int smemG  = STAGES * (BM * (BK + 4) + BK * (128 + 8)) * 4;
    const int smemHT = HST * (HBK * (HBM + 8) + HBK * (128 + 8)) * 2;
    const int smemHN = HST * (HBM * (HBK + 8) + HBK * (128 + 8)) * 2;

    static cudaStream_t s2 = nullptr;
    static cudaEvent_t evFork = nullptr, evSide = nullptr, evH = nullptr;
    static bool attr_done = false;
    if (!attr_done) {
        cudaFuncSetAttribute(gemm256,      cudaFuncAttributeMaxDynamicSharedMemorySize, smemG);
        cudaFuncSetAttribute(hgemm<true>,  cudaFuncAttributeMaxDynamicSharedMemorySize, smemHT);
        cudaFuncSetAttribute(hgemm<false>, cudaFuncAttributeMaxDynamicSharedMemorySize, smemHN);
        cudaStreamCreateWithFlags(&s2, cudaStreamNonBlocking);
        cudaEventCreateWithFlags(&evFork, cudaEventDisableTiming);
        cudaEventCreateWithFlags(&evSide, cudaEventDisableTiming);
        cudaEventCreateWithFlags(&evH, cudaEventDisableTiming);
        attr_done = true;
    }

    dim3 blk(256);
    int mt_n  = (N + BM - 1) / BM;      // 79 (tf32)
    int ht_n  = (N + HBM - 1) / HBM;    // 157
    int ht_e  = (E + HBM - 1) / HBM;    // 63
    const int S1 = 9;                   // trans split-K: 567 CTAs ~ 2 waves @2/SM
    const int S2 = 7;                   // non-trans: 1099 CTAs ~ 3.7 waves
    int ch1 = chunk64(N, S1);           // 2240
    int ch2 = chunk64(E, S2);           // 1152
    int zt_ = 256;
    int w_n4 = D * D / 4;
    const float margin1 = (float)S1;    // split-count bound for fused Mm amax

    // ---- fork: ALL prep + H conversion on side stream ----
    cudaEventRecord(evFork, 0);
    cudaStreamWaitEvent(s2, evFork, 0);
    {
        reset_amax4<<<1, 1, 0, s2>>>(sc);
        round_tf32_kernel<<<(w_n4 + 255) / 256, 256, 0, s2>>>(W1r, W1, w_n4);
        round_tf32_kernel<<<(w_n4 + 255) / 256, 256, 0, s2>>>(W2r, W2, w_n4);
        zero_kernel<<<(int)((ed + zt_ - 1) / zt_), zt_, 0, s2>>>(Mm0, (int)ed);
        zero_kernel<<<(int)((ed + zt_ - 1) / zt_), zt_, 0, s2>>>(Mm1, (int)ed);
        zero_kernel<<<(int)((nd + zt_ - 1) / zt_), zt_, 0, s2>>>(X1, (int)nd);
        zero_kernel<<<(int)((nd + zt_ - 1) / zt_), zt_, 0, s2>>>(X2, (int)nd);
        cudaEventRecord(evSide, s2);
        long long h8 = (long long)(ne / 8);
        f2h_dyn<<<(int)((h8 + 255) / 256), 256, 0, s2>>>(Hh, H, h8, nullptr);
        cudaEventRecord(evH, s2);
    }

    // ---- main chain ----
    int wt_n4 = T * D * D / 4;
    round_tf32_kernel<<<(wt_n4 + 255) / 256, 256>>>(Wtr, Wt, wt_n4);

    gemm256<<<dim3(mt_n, 1, T), blk, smemG>>>(
        emb, Wtr, X0, N, bt, nullptr, tid, D * D, D, nullptr);

    // join prep (W1r, zeros, amax resets)
    cudaStreamWaitEvent(0, evSide, 0);

    // ======== layer 1 ========
    gemm256<<<dim3(mt_n, 1, 1), blk, smemG>>>(
        X0, W1r, Yf, N, b1, dv, nullptr, 0, 0, amaxY0);
    f2h_dyn<<<(int)((nd / 8 + 255) / 256), 256>>>(Yh, Yf, (long long)(nd / 8), amaxY0);
    // join H conversion before first use
    cudaStreamWaitEvent(0, evH, 0);
    hgemm<true><<<dim3(ht_e, S1, 1), blk, smemHT>>>(
        Hh, Yh, Mm0, E, N, E, de, amaxY0, ch1, amaxM0, margin1);
    f2h_dyn<<<(int)((ed / 8 + 255) / 256), 256>>>(Mmh, Mm0, (long long)(ed / 8), amaxM0);
    hgemm<false><<<dim3(ht_n, S2, 1), blk, smemHN>>>(
        Hh, Mmh, X1, N, E, E, dv, amaxM0, ch2, nullptr, 1.f);

    // ======== layer 2 ========
    gemm256<<<dim3(mt_n, 1, 1), blk, smemG>>>(
        X1, W2r, Yf, N, b2, dv, nullptr, 0, 0, amaxY1);
    f2h_dyn<<<(int)((nd / 8 + 255) / 256), 256>>>(Yh, Yf, (long long)(nd / 8), amaxY1);
    hgemm<true><<<dim3(ht_e, S1, 1), blk, smemHT>>>(
        Hh, Yh, Mm1, E, N, E, de, amaxY1, ch1, amaxM1, margin1);
    f2h_dyn<<<(int)((ed / 8 + 255) / 256), 256>>>(Mmh, Mm1, (long long)(ed / 8), amaxM1);
    hgemm<false><<<dim3(ht_n, S2, 1), blk, smemHN>>>(
        Hh, Mmh, X2, N, E, E, dv, amaxM1, ch2, nullptr, 1.f);

    // ---- fusion ----
    fusion_kernel<<<(int)((nd + zt_ - 1) / zt_), zt_>>>(
        fw, X0, X1, X2, (float*)d_out, (int)nd);
}

// round 17
// speedup vs baseline: 1.0573x; 1.0190x over previous
#include <cuda_runtime.h>
#include <cuda_fp16.h>
#include <math.h>

// ----------------------------------------------------------------------------
// HyperGraphModel on GB300.
//  - 4 big H-GEMMs in fp16 (HMMA m16n8k16, fp32 accum, ldmatrix fragments,
//    3-stage BK=64 cp.async pipeline, ONE barrier per k-tile, 2 CTAs/SM).
//    4 warps/CTA with 64x64 warp tiles: LDSM crossbar traffic per tile drops
//    96KB -> 64KB (fewer warps duplicating fragments) while per-SM warp count
//    stays 8 (2 CTAs x 4 warps).
//  - Dynamic pow-2 scaling: amax fused into producing epilogues (split-K
//    bound: max|partial|*S >= true amax; exponent-only overshoot is free).
//  - H->fp16 conversion as ONE launch on a side stream; all scratch prep
//    rides the side stream too.
//  NOTE: tcgen05 unavailable — ptxas here targets sm_103 (no 'a').
// ----------------------------------------------------------------------------

#define BM 256           // tf32 kernel M tile
#define BK 32            // tf32 kernel k-tile
#define HBM 128          // fp16 kernel M tile (2 CTAs/SM)
#define HBK 64           // fp16 kernel k-tile
#define STAGES 3         // tf32 stages
#define HST 3            // fp16 stages

// fp32 scratch: X0,X1,X2,Yf (4*N*D) + Mm0 (E*D) + Mm1 (E*D) + Wtr + W1r + W2r
__device__ float g_buf[12500000];
// fp16 scratch: Hh (N*E) + Yh (N*D) + Mmh (E*D)
__device__ __align__(256) __half g_hbuf[163600000];
// scale slots: [0]=amaxY0 [1]=amaxY1 [2]=amaxM0 [3]=amaxM1
__device__ unsigned g_sc[8];

// ---------------- common helpers ----------------
__device__ __forceinline__ unsigned f2tf32(unsigned x) {
    unsigned r;
    asm("cvt.rna.tf32.f32 %0, %1;" : "=r"(r) : "r"(x));
    return r;
}
__device__ __forceinline__ float roundtf(float x) {
    return __uint_as_float(f2tf32(__float_as_uint(x)));
}
// scale exponent from raw amax bits: k such that amax*2^-k <= 16384 (4x margin)
__device__ __forceinline__ int amax_k(const unsigned* amaxPtr) {
    float m = __uint_as_float(*amaxPtr);
    int k = 0;
    if (m > 16384.f) k = (int)ceilf(log2f(m * (1.f / 16384.f)));
    if (k < 0) k = 0;
    return k;
}
__device__ __forceinline__ void mma_tf32(float* c, const unsigned* a, const unsigned* b) {
    asm volatile(
        "mma.sync.aligned.m16n8k8.row.col.f32.tf32.tf32.f32 "
        "{%0,%1,%2,%3}, {%4,%5,%6,%7}, {%8,%9}, {%0,%1,%2,%3};\n"
        : "+f"(c[0]), "+f"(c[1]), "+f"(c[2]), "+f"(c[3])
        : "r"(a[0]), "r"(a[1]), "r"(a[2]), "r"(a[3]), "r"(b[0]), "r"(b[1]));
}
__device__ __forceinline__ void mma_f16(float* c, const unsigned* a, const unsigned* b) {
    asm volatile(
        "mma.sync.aligned.m16n8k16.row.col.f32.f16.f16.f32 "
        "{%0,%1,%2,%3}, {%4,%5,%6,%7}, {%8,%9}, {%0,%1,%2,%3};\n"
        : "+f"(c[0]), "+f"(c[1]), "+f"(c[2]), "+f"(c[3])
        : "r"(a[0]), "r"(a[1]), "r"(a[2]), "r"(a[3]), "r"(b[0]), "r"(b[1]));
}
__device__ __forceinline__ void cpa16(void* dst, const void* src, bool pred) {
    unsigned daddr = (unsigned)__cvta_generic_to_shared(dst);
    int sz = pred ? 16 : 0;   // sz=0 -> 16B zero-fill (M/K edges)
    asm volatile("cp.async.cg.shared.global [%0], [%1], 16, %2;\n"
                 :: "r"(daddr), "l"(src), "r"(sz));
}
__device__ __forceinline__ void cpa_commit() {
    asm volatile("cp.async.commit_group;\n");
}
__device__ __forceinline__ void ldsm_x4(unsigned* r, unsigned a) {
    asm volatile("ldmatrix.sync.aligned.m8n8.x4.shared.b16 {%0,%1,%2,%3}, [%4];"
                 : "=r"(r[0]), "=r"(r[1]), "=r"(r[2]), "=r"(r[3]) : "r"(a));
}
__device__ __forceinline__ void ldsm_x4t(unsigned* r, unsigned a) {
    asm volatile("ldmatrix.sync.aligned.m8n8.x4.trans.shared.b16 {%0,%1,%2,%3}, [%4];"
                 : "=r"(r[0]), "=r"(r[1]), "=r"(r[2]), "=r"(r[3]) : "r"(a));
}

// ============================================================================
// fp16 GEMM: C[M,128] += 2^k(amaxIn) * rowscale[m] * (op(A)[M,K] @ B[K,128]),
// atomic split-K into pre-zeroed fp32 C. Optional fused amax of the partial
// contributions scaled by marginMul into amaxOut.
//  TRANS_A=false: A row-major [M,K] fp16 (lda = K)
//  TRANS_A=true : A stored [K,M] fp16, element (m,k) = A[k*lda+m]
// CTA tile 128x128x64, 4 warps (64x64 warp tile), 2 CTAs/SM, 3-stage cp.async.
// ============================================================================
template <bool TRANS_A>
__global__ void __launch_bounds__(128, 2)
hgemm(const __half* __restrict__ A, const __half* __restrict__ B,
      float* __restrict__ C, int M, int K, int lda,
      const float* __restrict__ rowscale, const unsigned* __restrict__ amaxIn,
      int kChunk, unsigned* __restrict__ amaxOut, float marginMul)
{
    constexpr int APITCH = TRANS_A ? (HBM + 8) : (HBK + 8);   // halves
    constexpr int ASZ = TRANS_A ? HBK * (HBM + 8) : HBM * (HBK + 8);
    constexpr int BPITCH = 128 + 8;
    constexpr int BSZ = HBK * BPITCH;
    extern __shared__ char smraw[];
    __half* hsm = (__half*)smraw;

    const int m0 = blockIdx.x * HBM;
    const int kBegin = blockIdx.y * kChunk;
    const int kEnd = min(K, kBegin + kChunk);
    if (kBegin >= K) return;
    const int kTiles = (kEnd - kBegin + HBK - 1) / HBK;

    const int tidx = threadIdx.x;
    const int lane = tidx & 31;
    const int wid  = tidx >> 5;       // 0..3
    const int g  = lane >> 2;
    const int tg = lane & 3;
    const int wm = wid & 1;           // warp row (64 M)
    const int wn = wid >> 1;          // warp col (64 N)
    const int lt = lane >> 3;
    const int lr = lane & 7;

    float acc[4][8][4];
#pragma unroll
    for (int mi = 0; mi < 4; mi++)
#pragma unroll
        for (int ni = 0; ni < 8; ni++)
#pragma unroll
            for (int j = 0; j < 4; j++) acc[mi][ni][j] = 0.f;

    auto load_tile = [&](int t, int stage) {
        int kt = kBegin + t * HBK;
        __half* as = hsm + stage * (ASZ + BSZ);
        __half* bs = as + ASZ;
        if (!TRANS_A) {
            // A [m][k]: 128 rows x 64 halves = 1024 x 16B chunks
#pragma unroll
            for (int i = 0; i < 8; i++) {
                int idx = tidx + i * 128;
                int m  = idx >> 3;               // 0..127
                int k8 = (idx & 7) << 3;         // 0..56
                bool p = (m0 + m < M) && (kt + k8 < kEnd);
                const __half* src = p ? &A[(size_t)(m0 + m) * lda + kt + k8] : A;
                cpa16(&as[m * APITCH + k8], src, p);
            }
        } else {
            // A [k][m]: 64 rows x 128 halves = 1024 chunks
#pragma unroll
            for (int i = 0; i < 8; i++) {
                int idx = tidx + i * 128;
                int k  = idx >> 4;               // 0..63
                int m8 = (idx & 15) << 3;        // 0..120
                int gm = m0 + m8;
                bool p = (gm < M) && (kt + k < kEnd);
                const __half* src = p ? &A[(size_t)(kt + k) * lda + gm] : A;
                cpa16(&as[k * APITCH + m8], src, p);
            }
        }
        // B [k][n]: 64 x 128 halves = 1024 chunks
#pragma unroll
        for (int i = 0; i < 8; i++) {
            int idx = tidx + i * 128;
            int k  = idx >> 4;                   // 0..63
            int n8 = (idx & 15) << 3;
            bool p = (kt + k < kEnd);
            const __half* src = p ? &B[(size_t)(kt + k) * 128 + n8] : (const __half*)B;
            cpa16(&bs[k * BPITCH + n8], src, p);
        }
        cpa_commit();
    };

    int pre = kTiles < (HST - 1) ? kTiles : (HST - 1);
    for (int t = 0; t < pre; t++) load_tile(t, t % HST);
    for (int t = pre; t < HST - 1; t++) cpa_commit();

    unsigned smBase = (unsigned)__cvta_generic_to_shared(hsm);

    for (int t = 0; t < kTiles; t++) {
        asm volatile("cp.async.wait_group %0;\n" :: "n"(HST - 2));
        __syncthreads();
        if (t + HST - 1 < kTiles) load_tile(t + HST - 1, (t + HST - 1) % HST);
        else cpa_commit();

        unsigned as_u = smBase + (unsigned)((t % HST) * (ASZ + BSZ) * 2);
        unsigned bs_u = as_u + ASZ * 2;

#pragma unroll
        for (int kk = 0; kk < HBK; kk += 16) {
            unsigned af[4][4];
#pragma unroll
            for (int mi = 0; mi < 4; mi++) {
                int bm = wm * 64 + mi * 16;
                if (!TRANS_A) {
                    unsigned a = as_u + (unsigned)(((bm + (lt & 1) * 8 + lr) * APITCH
                                                   + kk + (lt >> 1) * 8) * 2);
                    ldsm_x4(af[mi], a);
                } else {
                    unsigned a = as_u + (unsigned)(((kk + (lt >> 1) * 8 + lr) * APITCH
                                                   + bm + (lt & 1) * 8) * 2);
                    ldsm_x4t(af[mi], a);
                }
            }
            unsigned bf[8][2];
#pragma unroll
            for (int nj = 0; nj < 4; nj++) {
                unsigned r[4];
                unsigned a = bs_u + (unsigned)(((kk + (lt & 1) * 8 + lr) * BPITCH
                                               + wn * 64 + nj * 16 + (lt >> 1) * 8) * 2);
                ldsm_x4t(r, a);
                bf[2 * nj    ][0] = r[0]; bf[2 * nj    ][1] = r[1];
                bf[2 * nj + 1][0] = r[2]; bf[2 * nj + 1][1] = r[3];
            }
#pragma unroll
            for (int mi = 0; mi < 4; mi++)
#pragma unroll
                for (int ni = 0; ni < 8; ni++)
                    mma_f16(acc[mi][ni], af[mi], bf[ni]);
        }
    }

    // ---- epilogue: atomic split-K; optional fused amax of partials ----
    const float undo = ldexpf(1.f, amax_k(amaxIn));
    float lmax = 0.f;
#pragma unroll
    for (int mi = 0; mi < 4; mi++) {
#pragma unroll
        for (int h = 0; h < 2; h++) {
            int r = m0 + wm * 64 + mi * 16 + g + h * 8;
            if (r >= M) continue;
            float rs = rowscale[r] * undo;
#pragma unroll
            for (int ni = 0; ni < 8; ni++) {
                int cc = wn * 64 + ni * 8 + tg * 2;
                float v0 = acc[mi][ni][h * 2 + 0] * rs;
                float v1 = acc[mi][ni][h * 2 + 1] * rs;
                atomicAdd(&C[(size_t)r * 128 + cc    ], v0);
                atomicAdd(&C[(size_t)r * 128 + cc + 1], v1);
                lmax = fmaxf(lmax, fmaxf(fabsf(v0), fabsf(v1)));
            }
        }
    }
    if (amaxOut) {
        lmax *= marginMul;
#pragma unroll
        for (int o = 16; o; o >>= 1) lmax = fmaxf(lmax, __shfl_xor_sync(~0u, lmax, o));
        if (lane == 0) atomicMax(amaxOut, __float_as_uint(lmax));
    }
}

// ============================================================================
// tf32 GEMM for the small K=128 GEMMs (fp32 out) with FUSED absmax.
// ============================================================================
__global__ void __launch_bounds__(256, 1)
gemm256(const float* __restrict__ A, const float* __restrict__ B,
        float* __restrict__ C, int M,
        const float* __restrict__ bias, const float* __restrict__ rowscale,
        const int* __restrict__ rowsel, int ldbz, int biasz,
        unsigned* __restrict__ amaxOut)
{
    constexpr int K = 128;
    constexpr int APITCH = BK + 4;
    constexpr int ASZ = BM * APITCH;
    constexpr int BPITCH = 128 + 8;
    constexpr int BSZ = BK * BPITCH;
    extern __shared__ char smraw[];
    unsigned* sm = (unsigned*)smraw;

    const int m0 = blockIdx.x * BM;
    const int zt = blockIdx.z;
    B += (size_t)zt * ldbz;
    if (bias) bias += (size_t)zt * biasz;

    const int tidx = threadIdx.x;
    const int lane = tidx & 31;
    const int g  = lane >> 2;
    const int tg = lane & 3;
    const int wm = (tidx >> 5) & 3;
    const int wn = (tidx >> 7);

    float acc[4][8][4];
#pragma unroll
    for (int mi = 0; mi < 4; mi++)
#pragma unroll
        for (int ni = 0; ni < 8; ni++)
#pragma unroll
            for (int j = 0; j < 4; j++) acc[mi][ni][j] = 0.f;

    auto load_tile = [&](int t, int stage) {
        int kt = t * BK;
        unsigned* as = sm + stage * (ASZ + BSZ);
        unsigned* bs = as + ASZ;
#pragma unroll
        for (int i = 0; i < 8; i++) {
            int idx = tidx + i * 256;
            int m  = idx >> 3;
            int k4 = (idx & 7) << 2;
            bool p = (m0 + m < M);
            const float* src = p ? &A[(size_t)(m0 + m) * K + kt + k4] : A;
            cpa16(&as[m * APITCH + k4], src, p);
        }
#pragma unroll
        for (int i = 0; i < 4; i++) {
            int idx = tidx + i * 256;
            int k  = idx >> 5;
            int n4 = (idx & 31) << 2;
            cpa16(&bs[k * BPITCH + n4], &B[(size_t)(kt + k) * 128 + n4], true);
        }
        cpa_commit();
    };

    const int kTiles = K / BK;
    int pre = kTiles < (STAGES - 1) ? kTiles : (STAGES - 1);
    for (int t = 0; t < pre; t++) load_tile(t, t % STAGES);
    for (int t = pre; t < STAGES - 1; t++) cpa_commit();

    for (int t = 0; t < kTiles; t++) {
        asm volatile("cp.async.wait_group %0;\n" :: "n"(STAGES - 2));
        __syncthreads();
        if (t + STAGES - 1 < kTiles) load_tile(t + STAGES - 1, (t + STAGES - 1) % STAGES);
        else cpa_commit();

        const unsigned* as = sm + (t % STAGES) * (ASZ + BSZ);
        const unsigned* bs = as + ASZ;

#pragma unroll
        for (int kk = 0; kk < BK; kk += 8) {
            unsigned af[4][4];
#pragma unroll
            for (int mi = 0; mi < 4; mi++) {
                int bm = wm * 64 + mi * 16;
                af[mi][0] = f2tf32(as[(bm + g    ) * APITCH + kk + tg    ]);
                af[mi][1] = f2tf32(as[(bm + g + 8) * APITCH + kk + tg    ]);
                af[mi][2] = f2tf32(as[(bm + g    ) * APITCH + kk + tg + 4]);
                af[mi][3] = f2tf32(as[(bm + g + 8) * APITCH + kk + tg + 4]);
            }
            unsigned bf[8][2];
#pragma unroll
            for (int ni = 0; ni < 8; ni++) {
                int bn = wn * 64 + ni * 8;
                bf[ni][0] = bs[(kk + tg    ) * BPITCH + bn + g];
                bf[ni][1] = bs[(kk + tg + 4) * BPITCH + bn + g];
            }
#pragma unroll
            for (int mi = 0; mi < 4; mi++)
#pragma unroll
                for (int ni = 0; ni < 8; ni++)
                    mma_tf32(acc[mi][ni], af[mi], bf[ni]);
        }
    }

    float lmax = 0.f;
#pragma unroll
    for (int mi = 0; mi < 4; mi++) {
#pragma unroll
        for (int h = 0; h < 2; h++) {
            int r = m0 + wm * 64 + mi * 16 + g + h * 8;
            if (r >= M) continue;
            if (rowsel && rowsel[r] != zt) continue;
            float rs = rowscale ? rowscale[r] : 1.f;
#pragma unroll
            for (int ni = 0; ni < 8; ni++) {
                int cc = wn * 64 + ni * 8 + tg * 2;
                float v0 = acc[mi][ni][h * 2 + 0];
                float v1 = acc[mi][ni][h * 2 + 1];
                if (bias) { v0 += bias[cc]; v1 += bias[cc + 1]; }
                v0 *= rs; v1 *= rs;
                C[(size_t)r * 128 + cc    ] = v0;
                C[(size_t)r * 128 + cc + 1] = v1;
                lmax = fmaxf(lmax, fmaxf(fabsf(v0), fabsf(v1)));
            }
        }
    }
    if (amaxOut) {
#pragma unroll
        for (int o = 16; o; o >>= 1) lmax = fmaxf(lmax, __shfl_xor_sync(~0u, lmax, o));
        if (lane == 0) atomicMax(amaxOut, __float_as_uint(lmax));
    }
}

// ---------------- small kernels ----------------
__global__ void zero_kernel(float* __restrict__ p, int n) {
    int i = blockIdx.x * blockDim.x + threadIdx.x;
    if (i < n) p[i] = 0.f;
}
__global__ void reset_amax4(unsigned* slot) {
    slot[0] = 0u; slot[1] = 0u; slot[2] = 0u; slot[3] = 0u;
}

// fp32 -> fp16 (RN), scaled by 2^-k(amax) (amaxPtr null => scale 1)
__global__ void f2h_dyn(__half* __restrict__ dst, const float* __restrict__ src,
                        long long n8, const unsigned* __restrict__ amaxPtr) {
    float s = amaxPtr ? ldexpf(1.f, -amax_k(amaxPtr)) : 1.f;
    long long i = (long long)blockIdx.x * blockDim.x + threadIdx.x;
    if (i < n8) {
        float4 a = ((const float4*)src)[2 * i];
        float4 b = ((const float4*)src)[2 * i + 1];
        __half2 h[4];
        h[0] = __floats2half2_rn(a.x * s, a.y * s);
        h[1] = __floats2half2_rn(a.z * s, a.w * s);
        h[2] = __floats2half2_rn(b.x * s, b.y * s);
        h[3] = __floats2half2_rn(b.z * s, b.w * s);
        ((uint4*)dst)[i] = *(uint4*)h;
    }
}

__global__ void round_tf32_kernel(float* __restrict__ dst, const float* __restrict__ src, int n4) {
    int i = blockIdx.x * blockDim.x + threadIdx.x;
    if (i < n4) {
        float4 v = ((const float4*)src)[i];
        v.x = roundtf(v.x); v.y = roundtf(v.y);
        v.z = roundtf(v.z); v.w = roundtf(v.w);
        ((float4*)dst)[i] = v;
    }
}

__global__ void fusion_kernel(const float* __restrict__ fw,
                              const float* __restrict__ X0,
                              const float* __restrict__ X1,
                              const float* __restrict__ X2,
                              float* __restrict__ out, int n) {
    float f0 = fw[0], f1 = fw[1], f2 = fw[2];
    float mx = fmaxf(f0, fmaxf(f1, f2));
    float e0 = expf(f0 - mx), e1 = expf(f1 - mx), e2 = expf(f2 - mx);
    float inv = 1.f / (e0 + e1 + e2);
    float w0 = e0 * inv, w1 = e1 * inv, w2 = e2 * inv;
    int i = blockIdx.x * blockDim.x + threadIdx.x;
    if (i < n) out[i] = w0 * X0[i] + w1 * X1[i] + w2 * X2[i];
}

static inline int chunk64(int K, int S) {
    int tiles = (K + HBK - 1) / HBK;
    int per = (tiles + S - 1) / S;
    return per * HBK;
}

extern "C" void kernel_launch(void* const* d_in, const int* in_sizes, int n_in,
                              void* d_out, int out_size) {
    const float* emb = (const float*)d_in[0];
    const float* Wt  = (const float*)d_in[1];
    const float* bt  = (const float*)d_in[2];
    const float* W1  = (const float*)d_in[3];
    const float* b1  = (const float*)d_in[4];
    const float* W2  = (const float*)d_in[5];
    const float* b2  = (const float*)d_in[6];
    const float* fw  = (const float*)d_in[7];
    const float* H   = (const float*)d_in[8];
    const float* dv  = (const float*)d_in[9];
    const float* de  = (const float*)d_in[10];
    const int*   tid = (const int*)d_in[11];

    const int D = in_sizes[4];          // 128
    const int N = in_sizes[9];          // 20000
    const int E = in_sizes[10];         // 8000
    const int T = in_sizes[2] / D;      // 5

    float* buf = nullptr;
    cudaGetSymbolAddress((void**)&buf, g_buf);
    __half* hb = nullptr;
    cudaGetSymbolAddress((void**)&hb, g_hbuf);
    unsigned* sc = nullptr;
    cudaGetSymbolAddress((void**)&sc, g_sc);

    size_t nd = (size_t)N * D, ed = (size_t)E * D, ne = (size_t)N * E;
    float* X0  = buf;
    float* X1  = X0 + nd;
    float* X2  = X1 + nd;
    float* Yf  = X2 + nd;
    float* Mm0 = Yf + nd;
    float* Mm1 = Mm0 + ed;
    float* Wtr = Mm1 + ed;
    float* W1r = Wtr + (size_t)T * D * D;
    float* W2r = W1r + (size_t)D * D;
    __half* Hh  = hb;
    __half* Yh  = Hh + ne;
    __half* Mmh = Yh + nd;

    unsigned* amaxY0 = sc + 0;
    unsigned* amaxY1 = sc + 1;
    unsigned* amaxM0 = sc + 2;
    unsigned* amaxM1 = sc + 3;

    const int smemG  = STAGES * (BM * (BK + 4) + BK * (128 + 8)) * 4;
    const int smemHT = HST * (HBK * (HBM + 8) + HBK * (128 + 8)) * 2;
    const int smemHN = HST * (HBM * (HBK + 8) + HBK * (128 + 8)) * 2;

    static cudaStream_t s2 = nullptr;
    static cudaEvent_t evFork = nullptr, evSide = nullptr, evH = nullptr;
    static bool attr_done = false;
    if (!attr_done) {
        cudaFuncSetAttribute(gemm256,      cudaFuncAttributeMaxDynamicSharedMemorySize, smemG);
        cudaFuncSetAttribute(hgemm<true>,  cudaFuncAttributeMaxDynamicSharedMemorySize, smemHT);
        cudaFuncSetAttribute(hgemm<false>, cudaFuncAttributeMaxDynamicSharedMemorySize, smemHN);
        cudaStreamCreateWithFlags(&s2, cudaStreamNonBlocking);
        cudaEventCreateWithFlags(&evFork, cudaEventDisableTiming);
        cudaEventCreateWithFlags(&evSide, cudaEventDisableTiming);
        cudaEventCreateWithFlags(&evH, cudaEventDisableTiming);
        attr_done = true;
    }

    dim3 blk(256);
    dim3 hblk(128);                     // 4-warp hgemm CTAs
    int mt_n  = (N + BM - 1) / BM;      // 79 (tf32)
    int ht_n  = (N + HBM - 1) / HBM;    // 157
    int ht_e  = (E + HBM - 1) / HBM;    // 63
    const int S1 = 9;                   // trans split-K: 567 CTAs ~ 2 waves @2/SM
    const int S2 = 7;                   // non-trans: 1099 CTAs ~ 3.7 waves
    int ch1 = chunk64(N, S1);           // 2240
    int ch2 = chunk64(E, S2);           // 1152
    int zt_ = 256;
    int w_n4 = D * D / 4;
    const float margin1 = (float)S1;    // split-count bound for fused Mm amax

    // ---- fork: ALL prep + H conversion on side stream ----
    cudaEventRecord(evFork, 0);
    cudaStreamWaitEvent(s2, evFork, 0);
    {
        reset_amax4<<<1, 1, 0, s2>>>(sc);
        round_tf32_kernel<<<(w_n4 + 255) / 256, 256, 0, s2>>>(W1r, W1, w_n4);
        round_tf32_kernel<<<(w_n4 + 255) / 256, 256, 0, s2>>>(W2r, W2, w_n4);
        zero_kernel<<<(int)((ed + zt_ - 1) / zt_), zt_, 0, s2>>>(Mm0, (int)ed);
        zero_kernel<<<(int)((ed + zt_ - 1) / zt_), zt_, 0, s2>>>(Mm1, (int)ed);
        zero_kernel<<<(int)((nd + zt_ - 1) / zt_), zt_, 0, s2>>>(X1, (int)nd);
        zero_kernel<<<(int)((nd + zt_ - 1) / zt_), zt_, 0, s2>>>(X2, (int)nd);
        cudaEventRecord(evSide, s2);
        long long h8 = (long long)(ne / 8);
        f2h_dyn<<<(int)((h8 + 255) / 256), 256, 0, s2>>>(Hh, H, h8, nullptr);
        cudaEventRecord(evH, s2);
    }

    // ---- main chain ----
    int wt_n4 = T * D * D / 4;
    round_tf32_kernel<<<(wt_n4 + 255) / 256, 256>>>(Wtr, Wt, wt_n4);

    gemm256<<<dim3(mt_n, 1, T), blk, smemG>>>(
        emb, Wtr, X0, N, bt, nullptr, tid, D * D, D, nullptr);

    // join prep (W1r, zeros, amax resets)
    cudaStreamWaitEvent(0, evSide, 0);

    // ======== layer 1 ========
    gemm256<<<dim3(mt_n, 1, 1), blk, smemG>>>(
        X0, W1r, Yf, N, b1, dv, nullptr, 0, 0, amaxY0);
    f2h_dyn<<<(int)((nd / 8 + 255) / 256), 256>>>(Yh, Yf, (long long)(nd / 8), amaxY0);
    // join H conversion before first use
    cudaStreamWaitEvent(0, evH, 0);
    hgemm<true><<<dim3(ht_e, S1, 1), hblk, smemHT>>>(
        Hh, Yh, Mm0, E, N, E, de, amaxY0, ch1, amaxM0, margin1);
    f2h_dyn<<<(int)((ed / 8 + 255) / 256), 256>>>(Mmh, Mm0, (long long)(ed / 8), amaxM0);
    hgemm<false><<<dim3(ht_n, S2, 1), hblk, smemHN>>>(
        Hh, Mmh, X1, N, E, E, dv, amaxM0, ch2, nullptr, 1.f);

    // ======== layer 2 ========
    gemm256<<<dim3(mt_n, 1, 1), blk, smemG>>>(
        X1, W2r, Yf, N, b2, dv, nullptr, 0, 0, amaxY1);
    f2h_dyn<<<(int)((nd / 8 + 255) / 256), 256>>>(Yh, Yf, (long long)(nd / 8), amaxY1);
    hgemm<true><<<dim3(ht_e, S1, 1), hblk, smemHT>>>(
        Hh, Yh, Mm1, E, N, E, de, amaxY1, ch1, amaxM1, margin1);
    f2h_dyn<<<(int)((ed / 8 + 255) / 256), 256>>>(Mmh, Mm1, (long long)(ed / 8), amaxM1);
    hgemm<false><<<dim3(ht_n, S2, 1), hblk, smemHN>>>(
        Hh, Mmh, X2, N, E, E, dv, amaxM1, ch2, nullptr, 1.f);

    // ---- fusion ----
    fusion_kernel<<<(int)((nd + zt_ - 1) / zt_), zt_>>>(
        fw, X0, X1, X2, (float*)d_out, (int)nd);
}